// round 14
// baseline (speedup 1.0000x reference)
#include <cuda_runtime.h>
#include <cuda_fp16.h>
#include <cstdint>

typedef unsigned long long ull;

// ---------------- problem constants ----------------
#define NQ 8100
#define NK 8100
#define D_ 147
#define HO 90
#define H  96
#define NPIX (H * H)       // 9216

#define KT    448          // fp16: [b(147)|s(147)|b(147)|kn cols|pad]
#define NR    8192
#define BM    128
#define BN    128
#define BK    64
#define KTILES 7           // 448/64

// ---------------- device scratch ----------------
__device__ __align__(256) __half g_A[(size_t)NR * KT];  // [qb | qs | qb | 1 1 0..]
__device__ __align__(256) __half g_B[(size_t)NR * KT];  // [kb | kb | ks | -kn/2 split]
__device__ ull   g_cand[NR];

// ---------------- compile-time k -> (term, kk, qoff) LUT ----------------
// bits[28:30]=term (0=big,1=small,2=big-copy,3=pad/kn), bits[16:24]=kk, bits[0:15]=qoff
struct LutT { uint32_t v[KT]; };
constexpr LutT make_lut() {
    LutT l{};
    for (int k = 0; k < KT; ++k) {
        if (k >= 441) { l.v[k] = 3u << 28; continue; }
        int term = 0, kk = k;
        if (k >= 294)      { term = 2; kk = k - 294; }
        else if (k >= 147) { term = 1; kk = k - 147; }
        int c = kk / 49, rr = kk % 49, i = rr / 7, j = rr % 7;
        uint32_t qoff = (uint32_t)(c * NPIX + i * H + j);
        l.v[k] = ((uint32_t)term << 28) | ((uint32_t)kk << 16) | qoff;
    }
    return l;
}
__device__ const LutT d_lut = make_lut();

// ---------------- helpers ----------------
__device__ __forceinline__ uint32_t smem_u32(const void* p) {
    uint32_t a;
    asm("{ .reg .u64 t; cvta.to.shared.u64 t, %1; cvt.u32.u64 %0, t; }" : "=r"(a) : "l"(p));
    return a;
}
__device__ __forceinline__ unsigned fkey(float f) {
    unsigned u = __float_as_uint(f);
    return (u & 0x80000000u) ? ~u : (u | 0x80000000u);
}
__device__ __forceinline__ void cp16(uint32_t dst, const void* src) {
    asm volatile("cp.async.cg.shared.global [%0], [%1], 16;" :: "r"(dst), "l"(src));
}
__device__ __forceinline__ void ldmatrix_x4(uint32_t* r, uint32_t addr) {
    asm volatile("ldmatrix.sync.aligned.m8n8.x4.shared.b16 {%0,%1,%2,%3}, [%4];"
                 : "=r"(r[0]), "=r"(r[1]), "=r"(r[2]), "=r"(r[3]) : "r"(addr));
}
__device__ __forceinline__ void mma_f16(float* c, const uint32_t* a, uint32_t b0, uint32_t b1) {
    asm volatile(
        "mma.sync.aligned.m16n8k16.row.col.f32.f16.f16.f32 "
        "{%0,%1,%2,%3}, {%4,%5,%6,%7}, {%8,%9}, {%0,%1,%2,%3};"
        : "+f"(c[0]), "+f"(c[1]), "+f"(c[2]), "+f"(c[3])
        : "r"(a[0]), "r"(a[1]), "r"(a[2]), "r"(a[3]), "r"(b0), "r"(b1));
}

// ---------------- fused prep: LUT-driven A/B vec8 + kn + g_cand init + out zero ----------------
__global__ void prep_AB_kernel(const float* __restrict__ query,
                               const float* __restrict__ key,
                               float* __restrict__ out) {
    int t = blockIdx.x * 256 + threadIdx.x;          // t < NR*KT/8
    int p  = t / (KT / 8);
    int k0 = (t - p * (KT / 8)) * 8;
    const bool pq = (p < NQ);
    const bool pk = (p < NK);
    const int ppos = pq ? (p / HO) * H + (p % HO) : 0;   // pi*96 + pj
    const float* krow = key + (size_t)p * D_;

    const __half one  = __float2half_rn(1.0f);
    const __half zero = __float2half_rn(0.0f);
    __half va[8], vb[8];
    #pragma unroll
    for (int j = 0; j < 8; ++j) {
        int k = k0 + j;
        uint32_t u = __ldg(&d_lut.v[k]);
        uint32_t term = u >> 28;
        if (term == 3u) {
            va[j] = (k <= 442) ? one : zero;
            vb[j] = zero;
        } else {
            float xq = pq ? __ldg(query + (u & 0x7fffu) + ppos) : 0.0f;
            __half bq = __float2half_rn(xq);
            va[j] = (term == 1u) ? __float2half_rn(xq - __half2float(bq)) : bq;
            float xk = pk ? __ldg(krow + ((u >> 16) & 0xffu)) : 0.0f;
            __half bk = __float2half_rn(xk);
            vb[j] = (term == 2u) ? __float2half_rn(xk - __half2float(bk)) : bk;
        }
    }
    // thread owning k 440..447 writes kn columns (441,442)
    if (k0 == 440) {
        if (pk) {
            float s0 = 0.0f, s1 = 0.0f, s2 = 0.0f, s3 = 0.0f;
            #pragma unroll
            for (int d = 0; d < 144; d += 4) {
                float v0 = __ldg(krow + d),     v1 = __ldg(krow + d + 1);
                float v2 = __ldg(krow + d + 2), v3 = __ldg(krow + d + 3);
                s0 = fmaf(v0, v0, s0); s1 = fmaf(v1, v1, s1);
                s2 = fmaf(v2, v2, s2); s3 = fmaf(v3, v3, s3);
            }
            float v0 = __ldg(krow + 144), v1 = __ldg(krow + 145), v2 = __ldg(krow + 146);
            s0 = fmaf(v0, v0, s0); s1 = fmaf(v1, v1, s1); s2 = fmaf(v2, v2, s2);
            float h = -0.5f * ((s0 + s1) + (s2 + s3));
            __half b1 = __float2half_rn(h);
            __half b2 = __float2half_rn(h - __half2float(b1));
            vb[1] = b1;
            vb[2] = b2;
        } else {
            vb[1] = __float2half_rn(-60000.0f);   // sentinel: pad rows never win
        }
    }
    *reinterpret_cast<uint4*>(&g_A[(size_t)p * KT + k0]) = *reinterpret_cast<uint4*>(va);
    *reinterpret_cast<uint4*>(&g_B[(size_t)p * KT + k0]) = *reinterpret_cast<uint4*>(vb);
    if (t < NR) g_cand[t] = 0xFFFFFFFFFFFFFFFFull;
    if (t < 3 * NPIX) out[t] = 0.0f;
}

// ---------------- main mma.sync fp16 GEMM + argmax(acc) ----------------
// smem: 3 x (As 16KB | Bs 16KB)
#define BUF_BYTES 32768
#define SMEM_TOTAL (3 * BUF_BYTES)

__global__ __launch_bounds__(256, 2) void nn_mma_kernel() {
    extern __shared__ __align__(128) char smem[];
    uint32_t sb = smem_u32(smem);

    const int tid = threadIdx.x;
    const int l   = tid & 31;
    const int wid = tid >> 5;
    const int wm  = wid & 3;    // 4 M-warps (32 rows each)
    const int wn  = wid >> 2;   // 2 N-warps (64 cols each)
    const int m0  = blockIdx.x * BM;
    const int n0  = blockIdx.y * BN;

    const __half* Ag = g_A + (size_t)m0 * KT;
    const __half* Bg = g_B + (size_t)n0 * KT;

    const int a_r  = (l & 7) | (((l >> 3) & 1) << 3);
    const int a_kh = (l >> 4) & 1;
    const int b_r  = (l & 7) | (((l >> 4) & 1) << 3);
    const int b_kh = (l >> 3) & 1;

    float acc[2][8][4];
    #pragma unroll
    for (int mi = 0; mi < 2; ++mi)
        #pragma unroll
        for (int ni = 0; ni < 8; ++ni)
            #pragma unroll
            for (int c = 0; c < 4; ++c) acc[mi][ni][c] = 0.0f;

    auto issue = [&](int kt) {
        uint32_t ab = sb + (uint32_t)(kt % 3) * BUF_BYTES;
        uint32_t bb = ab + 16384;
        const __half* As = Ag + kt * BK;
        const __half* Bs = Bg + kt * BK;
        #pragma unroll
        for (int i = tid; i < 1024; i += 256) {
            int r = i >> 3, c = i & 7;
            uint32_t off = ((uint32_t)r << 7) | ((uint32_t)(c ^ (r & 7)) << 4);
            cp16(ab + off, As + (size_t)r * KT + c * 8);
            cp16(bb + off, Bs + (size_t)r * KT + c * 8);
        }
        asm volatile("cp.async.commit_group;" ::: "memory");
    };

    issue(0);
    issue(1);

    for (int kt = 0; kt < KTILES; ++kt) {
        if (kt + 1 < KTILES) {
            asm volatile("cp.async.wait_group 1;" ::: "memory");
        } else {
            asm volatile("cp.async.wait_group 0;" ::: "memory");
        }
        __syncthreads();

        if (kt + 2 < KTILES) issue(kt + 2);

        uint32_t ab = sb + (uint32_t)(kt % 3) * BUF_BYTES;
        uint32_t bb = ab + 16384;

        #pragma unroll
        for (int ks = 0; ks < 4; ++ks) {
            uint32_t a[2][4];
            #pragma unroll
            for (int mi = 0; mi < 2; ++mi) {
                int row = wm * 32 + mi * 16 + a_r;
                uint32_t chunk = (uint32_t)((ks * 2 + a_kh) ^ (row & 7));
                ldmatrix_x4(a[mi], ab + ((uint32_t)row << 7) + (chunk << 4));
            }
            #pragma unroll
            for (int nj = 0; nj < 4; ++nj) {
                uint32_t b4[4];
                int nrow = wn * 64 + nj * 16 + b_r;
                uint32_t chunk = (uint32_t)((ks * 2 + b_kh) ^ (nrow & 7));
                ldmatrix_x4(b4, bb + ((uint32_t)nrow << 7) + (chunk << 4));
                #pragma unroll
                for (int mi = 0; mi < 2; ++mi) {
                    mma_f16(acc[mi][2 * nj],     a[mi], b4[0], b4[1]);
                    mma_f16(acc[mi][2 * nj + 1], a[mi], b4[2], b4[3]);
                }
            }
        }
        // no trailing sync: next iteration's sync protects buffer reuse
    }

    // ---- argmax(acc) epilogue (kn folded into GEMM) ----
    const int q = l & 3, g = l >> 2;
    float best[4];
    int   bidx[4];
    #pragma unroll
    for (int s = 0; s < 4; ++s) { best[s] = -3.402823466e38f; bidx[s] = 0; }

    #pragma unroll
    for (int mi = 0; mi < 2; ++mi) {
        #pragma unroll
        for (int ni = 0; ni < 8; ++ni) {
            int col0 = n0 + wn * 64 + ni * 8 + q * 2;
            #pragma unroll
            for (int h = 0; h < 2; ++h) {
                int s = mi * 2 + h;
                float a0 = acc[mi][ni][h * 2];
                float a1 = acc[mi][ni][h * 2 + 1];
                if (a0 > best[s]) { best[s] = a0; bidx[s] = col0; }
                if (a1 > best[s]) { best[s] = a1; bidx[s] = col0 + 1; }
            }
        }
    }

    #pragma unroll
    for (int s = 0; s < 4; ++s) {
        float b = best[s];
        int   i = bidx[s];
        #pragma unroll
        for (int off = 1; off <= 2; off <<= 1) {
            float ob = __shfl_xor_sync(0xffffffffu, b, off);
            int   oi = __shfl_xor_sync(0xffffffffu, i, off);
            if (ob > b || (ob == b && oi < i)) { b = ob; i = oi; }
        }
        if (q == 0) {
            int row = m0 + wm * 32 + (s >> 1) * 16 + (s & 1) * 8 + g;
            if (row < NQ)
                atomicMin(&g_cand[row], (((ull)fkey(-b)) << 32) | (unsigned)i);
        }
    }
}

// ---------------- fold scatter: one warp per patch, pre-divided atomics ----------------
__global__ void scatter_kernel(const float* __restrict__ value, float* __restrict__ out) {
    int w    = blockIdx.x * 8 + (threadIdx.x >> 5);   // patch index
    int lane = threadIdx.x & 31;
    if (w >= NQ) return;
    int row = (int)(unsigned)(g_cand[w] & 0xffffffffull);
    int pi = w / HO, pj = w - (w / HO) * HO;
    const float* vr = value + (size_t)row * D_;
    #pragma unroll
    for (int e = lane; e < D_; e += 32) {
        uint32_t u = __ldg(&d_lut.v[e]);           // term=0 entries: qoff = c*9216+i*96+j
        int y = pi + ((int)(u & 0x7fffu) % NPIX) / H;
        int c = (int)(u & 0x7fffu) / NPIX;
        int x = pj + ((int)(u & 0x7fffu) % H);
        int npi = min(HO - 1, y) - max(0, y - 6) + 1;
        int npj = min(HO - 1, x) - max(0, x - 6) + 1;
        float inv = __frcp_rn((float)(npi * npj));
        atomicAdd(&out[c * NPIX + y * H + x], __ldg(vr + e) * inv);
    }
}

// ---------------- launch ----------------
extern "C" void kernel_launch(void* const* d_in, const int* in_sizes, int n_in,
                              void* d_out, int out_size) {
    const float* query = (const float*)d_in[0];
    const float* key   = (const float*)d_in[1];
    const float* value = (const float*)d_in[2];
    float* out = (float*)d_out;

    {
        int n8 = NR * KT / 8;                      // 458,752 threads
        prep_AB_kernel<<<n8 / 256, 256>>>(query, key, out);
    }
    {
        cudaFuncSetAttribute(nn_mma_kernel,
                             cudaFuncAttributeMaxDynamicSharedMemorySize, SMEM_TOTAL);
        dim3 grid(NR / BM, NR / BN);               // 64 x 64
        nn_mma_kernel<<<grid, 256, SMEM_TOTAL>>>();
    }
    {
        scatter_kernel<<<(NQ + 7) / 8, 256>>>(value, out);
    }
}

// round 15
// speedup vs baseline: 1.0481x; 1.0481x over previous
#include <cuda_runtime.h>
#include <cuda_fp16.h>
#include <cstdint>

typedef unsigned long long ull;

// ---------------- problem constants ----------------
#define NQ 8100
#define NK 8100
#define D_ 147
#define HO 90
#define H  96
#define NPIX (H * H)       // 9216

#define KT    448          // fp16: [b(147)|s(147)|b(147)|kn cols|pad]
#define NR    8192
#define BM    128
#define BN    128
#define BK    64
#define KTILES 7           // 448/64

// ---------------- device scratch ----------------
__device__ __align__(256) __half g_A[(size_t)NR * KT];  // [qb | qs | qb | 1 1 0..]
__device__ __align__(256) __half g_B[(size_t)NR * KT];  // [kb | kb | ks | -kn/2 split]
__device__ ull   g_cand[NR];

// ---------------- compile-time e(0..146) -> query pixel offset LUT ----------------
struct LutT { uint32_t v[160]; };
constexpr LutT make_lut() {
    LutT l{};
    for (int e = 0; e < 147; ++e) {
        int c = e / 49, rr = e % 49, i = rr / 7, j = rr % 7;
        l.v[e] = (uint32_t)(c * NPIX + i * H + j);
    }
    return l;
}
__device__ const LutT d_lut = make_lut();

// ---------------- helpers ----------------
__device__ __forceinline__ uint32_t smem_u32(const void* p) {
    uint32_t a;
    asm("{ .reg .u64 t; cvta.to.shared.u64 t, %1; cvt.u32.u64 %0, t; }" : "=r"(a) : "l"(p));
    return a;
}
__device__ __forceinline__ unsigned fkey(float f) {
    unsigned u = __float_as_uint(f);
    return (u & 0x80000000u) ? ~u : (u | 0x80000000u);
}
__device__ __forceinline__ void cp16(uint32_t dst, const void* src) {
    asm volatile("cp.async.cg.shared.global [%0], [%1], 16;" :: "r"(dst), "l"(src));
}
__device__ __forceinline__ void ldmatrix_x4(uint32_t* r, uint32_t addr) {
    asm volatile("ldmatrix.sync.aligned.m8n8.x4.shared.b16 {%0,%1,%2,%3}, [%4];"
                 : "=r"(r[0]), "=r"(r[1]), "=r"(r[2]), "=r"(r[3]) : "r"(addr));
}
__device__ __forceinline__ void mma_f16(float* c, const uint32_t* a, uint32_t b0, uint32_t b1) {
    asm volatile(
        "mma.sync.aligned.m16n8k16.row.col.f32.f16.f16.f32 "
        "{%0,%1,%2,%3}, {%4,%5,%6,%7}, {%8,%9}, {%0,%1,%2,%3};"
        : "+f"(c[0]), "+f"(c[1]), "+f"(c[2]), "+f"(c[3])
        : "r"(a[0]), "r"(a[1]), "r"(a[2]), "r"(a[3]), "r"(b0), "r"(b1));
}

// ---------------- prep: one warp per row, smem-staged, coalesced ----------------
__global__ void prep_AB_kernel(const float* __restrict__ query,
                               const float* __restrict__ key,
                               float* __restrict__ out) {
    __shared__ float sq[8][148];
    __shared__ float sk[8][148];
    const int lane = threadIdx.x & 31;
    const int w    = threadIdx.x >> 5;
    const int p    = blockIdx.x * 8 + w;
    const bool pq  = (p < NQ);
    const bool pk  = (p < NK);

    // stage key row (coalesced) and query patch gather
    const float* krow = key + (size_t)p * D_;
    const int ppos = pq ? (p / HO) * H + (p % HO) : 0;
    #pragma unroll
    for (int e = lane; e < 147; e += 32) {
        sk[w][e] = pk ? __ldg(krow + e) : 0.0f;
        sq[w][e] = pq ? __ldg(query + d_lut.v[e] + ppos) : 0.0f;
    }
    __syncwarp();

    // ||k||^2 via warp xor-reduce (all lanes end with s)
    float s = 0.0f;
    #pragma unroll
    for (int e = lane; e < 147; e += 32) {
        float v = sk[w][e];
        s = fmaf(v, v, s);
    }
    #pragma unroll
    for (int off = 16; off > 0; off >>= 1)
        s += __shfl_xor_sync(0xffffffffu, s, off);
    const float hkn = -0.5f * s;
    const __half kb1 = __float2half_rn(hkn);
    const __half kb2 = __float2half_rn(hkn - __half2float(kb1));

    // write phase: lanes 0..27 emit 16 elements each (2 x uint4 per matrix)
    if (lane < 28) {
        #pragma unroll
        for (int g2 = 0; g2 < 2; ++g2) {
            int k0 = lane * 16 + g2 * 8;
            __half va[8], vb[8];
            #pragma unroll
            for (int j = 0; j < 8; ++j) {
                int k = k0 + j;
                if (k < 441) {
                    int term, kk;
                    if (k < 147)      { term = 0; kk = k; }
                    else if (k < 294) { term = 1; kk = k - 147; }
                    else              { term = 2; kk = k - 294; }
                    float xq = sq[w][kk];
                    __half bq = __float2half_rn(xq);
                    va[j] = (term == 1) ? __float2half_rn(xq - __half2float(bq)) : bq;
                    float xk = sk[w][kk];
                    __half bk = __float2half_rn(xk);
                    vb[j] = (term == 2) ? __float2half_rn(xk - __half2float(bk)) : bk;
                } else if (k == 441) {
                    va[j] = __float2half_rn(1.0f);
                    vb[j] = pk ? kb1 : __float2half_rn(-60000.0f);  // sentinel pad rows
                } else if (k == 442) {
                    va[j] = __float2half_rn(1.0f);
                    vb[j] = pk ? kb2 : __float2half_rn(0.0f);
                } else {
                    va[j] = __float2half_rn(0.0f);
                    vb[j] = __float2half_rn(0.0f);
                }
            }
            *reinterpret_cast<uint4*>(&g_A[(size_t)p * KT + k0]) = *reinterpret_cast<uint4*>(va);
            *reinterpret_cast<uint4*>(&g_B[(size_t)p * KT + k0]) = *reinterpret_cast<uint4*>(vb);
        }
    }

    // init g_cand and zero out (1024 blocks x 256 threads)
    int t = blockIdx.x * 256 + threadIdx.x;
    if (t < NR) g_cand[t] = 0xFFFFFFFFFFFFFFFFull;
    if (t < 3 * NPIX) out[t] = 0.0f;
}

// ---------------- main mma.sync fp16 GEMM + argmax(acc) ----------------
// smem: 3 x (As 16KB | Bs 16KB)
#define BUF_BYTES 32768
#define SMEM_TOTAL (3 * BUF_BYTES)

__global__ __launch_bounds__(256, 2) void nn_mma_kernel() {
    extern __shared__ __align__(128) char smem[];
    uint32_t sb = smem_u32(smem);

    const int tid = threadIdx.x;
    const int l   = tid & 31;
    const int wid = tid >> 5;
    const int wm  = wid & 3;    // 4 M-warps (32 rows each)
    const int wn  = wid >> 2;   // 2 N-warps (64 cols each)
    const int m0  = blockIdx.x * BM;
    const int n0  = blockIdx.y * BN;

    const __half* Ag = g_A + (size_t)m0 * KT;
    const __half* Bg = g_B + (size_t)n0 * KT;

    const int a_r  = (l & 7) | (((l >> 3) & 1) << 3);
    const int a_kh = (l >> 4) & 1;
    const int b_r  = (l & 7) | (((l >> 4) & 1) << 3);
    const int b_kh = (l >> 3) & 1;

    float acc[2][8][4];
    #pragma unroll
    for (int mi = 0; mi < 2; ++mi)
        #pragma unroll
        for (int ni = 0; ni < 8; ++ni)
            #pragma unroll
            for (int c = 0; c < 4; ++c) acc[mi][ni][c] = 0.0f;

    auto issue = [&](int kt) {
        uint32_t ab = sb + (uint32_t)(kt % 3) * BUF_BYTES;
        uint32_t bb = ab + 16384;
        const __half* As = Ag + kt * BK;
        const __half* Bs = Bg + kt * BK;
        #pragma unroll
        for (int i = tid; i < 1024; i += 256) {
            int r = i >> 3, c = i & 7;
            uint32_t off = ((uint32_t)r << 7) | ((uint32_t)(c ^ (r & 7)) << 4);
            cp16(ab + off, As + (size_t)r * KT + c * 8);
            cp16(bb + off, Bs + (size_t)r * KT + c * 8);
        }
        asm volatile("cp.async.commit_group;" ::: "memory");
    };

    issue(0);
    issue(1);

    for (int kt = 0; kt < KTILES; ++kt) {
        if (kt + 1 < KTILES) {
            asm volatile("cp.async.wait_group 1;" ::: "memory");
        } else {
            asm volatile("cp.async.wait_group 0;" ::: "memory");
        }
        __syncthreads();

        if (kt + 2 < KTILES) issue(kt + 2);

        uint32_t ab = sb + (uint32_t)(kt % 3) * BUF_BYTES;
        uint32_t bb = ab + 16384;

        #pragma unroll
        for (int ks = 0; ks < 4; ++ks) {
            uint32_t a[2][4];
            #pragma unroll
            for (int mi = 0; mi < 2; ++mi) {
                int row = wm * 32 + mi * 16 + a_r;
                uint32_t chunk = (uint32_t)((ks * 2 + a_kh) ^ (row & 7));
                ldmatrix_x4(a[mi], ab + ((uint32_t)row << 7) + (chunk << 4));
            }
            #pragma unroll
            for (int nj = 0; nj < 4; ++nj) {
                uint32_t b4[4];
                int nrow = wn * 64 + nj * 16 + b_r;
                uint32_t chunk = (uint32_t)((ks * 2 + b_kh) ^ (nrow & 7));
                ldmatrix_x4(b4, bb + ((uint32_t)nrow << 7) + (chunk << 4));
                #pragma unroll
                for (int mi = 0; mi < 2; ++mi) {
                    mma_f16(acc[mi][2 * nj],     a[mi], b4[0], b4[1]);
                    mma_f16(acc[mi][2 * nj + 1], a[mi], b4[2], b4[3]);
                }
            }
        }
        // no trailing sync: next iteration's sync protects buffer reuse
    }

    // ---- argmax(acc) epilogue (kn folded into GEMM) ----
    const int q = l & 3, g = l >> 2;
    float best[4];
    int   bidx[4];
    #pragma unroll
    for (int s = 0; s < 4; ++s) { best[s] = -3.402823466e38f; bidx[s] = 0; }

    #pragma unroll
    for (int mi = 0; mi < 2; ++mi) {
        #pragma unroll
        for (int ni = 0; ni < 8; ++ni) {
            int col0 = n0 + wn * 64 + ni * 8 + q * 2;
            #pragma unroll
            for (int h = 0; h < 2; ++h) {
                int s = mi * 2 + h;
                float a0 = acc[mi][ni][h * 2];
                float a1 = acc[mi][ni][h * 2 + 1];
                if (a0 > best[s]) { best[s] = a0; bidx[s] = col0; }
                if (a1 > best[s]) { best[s] = a1; bidx[s] = col0 + 1; }
            }
        }
    }

    #pragma unroll
    for (int s = 0; s < 4; ++s) {
        float b = best[s];
        int   i = bidx[s];
        #pragma unroll
        for (int off = 1; off <= 2; off <<= 1) {
            float ob = __shfl_xor_sync(0xffffffffu, b, off);
            int   oi = __shfl_xor_sync(0xffffffffu, i, off);
            if (ob > b || (ob == b && oi < i)) { b = ob; i = oi; }
        }
        if (q == 0) {
            int row = m0 + wm * 32 + (s >> 1) * 16 + (s & 1) * 8 + g;
            if (row < NQ)
                atomicMin(&g_cand[row], (((ull)fkey(-b)) << 32) | (unsigned)i);
        }
    }
}

// ---------------- fold scatter: one warp per patch, pre-divided atomics ----------------
__global__ void scatter_kernel(const float* __restrict__ value, float* __restrict__ out) {
    int w    = blockIdx.x * 8 + (threadIdx.x >> 5);   // patch index
    int lane = threadIdx.x & 31;
    if (w >= NQ) return;
    int row = (int)(unsigned)(g_cand[w] & 0xffffffffull);
    int pi = w / HO, pj = w - (w / HO) * HO;
    const float* vr = value + (size_t)row * D_;
    #pragma unroll
    for (int e = lane; e < D_; e += 32) {
        uint32_t u = __ldg(&d_lut.v[e]);           // qoff = c*9216 + i*96 + j
        int c = (int)u / NPIX;
        int rem = (int)u - c * NPIX;
        int y = pi + rem / H;
        int x = pj + (rem - (rem / H) * H);
        int npi = min(HO - 1, y) - max(0, y - 6) + 1;
        int npj = min(HO - 1, x) - max(0, x - 6) + 1;
        float inv = __frcp_rn((float)(npi * npj));
        atomicAdd(&out[c * NPIX + y * H + x], __ldg(vr + e) * inv);
    }
}

// ---------------- launch ----------------
extern "C" void kernel_launch(void* const* d_in, const int* in_sizes, int n_in,
                              void* d_out, int out_size) {
    const float* query = (const float*)d_in[0];
    const float* key   = (const float*)d_in[1];
    const float* value = (const float*)d_in[2];
    float* out = (float*)d_out;

    {
        prep_AB_kernel<<<NR / 8, 256>>>(query, key, out);   // 1024 blocks, warp-per-row
    }
    {
        cudaFuncSetAttribute(nn_mma_kernel,
                             cudaFuncAttributeMaxDynamicSharedMemorySize, SMEM_TOTAL);
        dim3 grid(NR / BM, NR / BN);               // 64 x 64
        nn_mma_kernel<<<grid, 256, SMEM_TOTAL>>>();
    }
    {
        scatter_kernel<<<(NQ + 7) / 8, 256>>>(value, out);
    }
}

// round 16
// speedup vs baseline: 1.1873x; 1.1328x over previous
#include <cuda_runtime.h>
#include <cuda_fp16.h>
#include <cstdint>

typedef unsigned long long ull;

// ---------------- problem constants ----------------
#define NQ 8100
#define NK 8100
#define D_ 147
#define HO 90
#define H  96
#define NPIX (H * H)       // 9216

#define KT    448          // fp16: [b(147)|s(147)|b(147)|kn cols|pad]
#define NR    8192
#define BM    128
#define BN    128
#define BK    64
#define KTILES 7           // 448/64

// ---------------- device scratch ----------------
__device__ __align__(256) __half g_A[(size_t)NR * KT];  // [qb | qs | qb | 1 1 0..]
__device__ __align__(256) __half g_B[(size_t)NR * KT];  // [kb | kb | ks | -kn/2 split]
__device__ ull   g_cand[NR];

// ---------------- compile-time e(0..146) -> query pixel offset LUT ----------------
struct LutT { uint32_t v[160]; };
constexpr LutT make_lut() {
    LutT l{};
    for (int e = 0; e < 147; ++e) {
        int c = e / 49, rr = e % 49, i = rr / 7, j = rr % 7;
        l.v[e] = (uint32_t)(c * NPIX + i * H + j);
    }
    return l;
}
__device__ const LutT d_lut = make_lut();

// ---------------- helpers ----------------
__device__ __forceinline__ uint32_t smem_u32(const void* p) {
    uint32_t a;
    asm("{ .reg .u64 t; cvta.to.shared.u64 t, %1; cvt.u32.u64 %0, t; }" : "=r"(a) : "l"(p));
    return a;
}
__device__ __forceinline__ unsigned fkey(float f) {
    unsigned u = __float_as_uint(f);
    return (u & 0x80000000u) ? ~u : (u | 0x80000000u);
}
__device__ __forceinline__ void cp16(uint32_t dst, const void* src) {
    asm volatile("cp.async.cg.shared.global [%0], [%1], 16;" :: "r"(dst), "l"(src));
}
__device__ __forceinline__ void ldmatrix_x4(uint32_t* r, uint32_t addr) {
    asm volatile("ldmatrix.sync.aligned.m8n8.x4.shared.b16 {%0,%1,%2,%3}, [%4];"
                 : "=r"(r[0]), "=r"(r[1]), "=r"(r[2]), "=r"(r[3]) : "r"(addr));
}
__device__ __forceinline__ void mma_f16(float* c, const uint32_t* a, uint32_t b0, uint32_t b1) {
    asm volatile(
        "mma.sync.aligned.m16n8k16.row.col.f32.f16.f16.f32 "
        "{%0,%1,%2,%3}, {%4,%5,%6,%7}, {%8,%9}, {%0,%1,%2,%3};"
        : "+f"(c[0]), "+f"(c[1]), "+f"(c[2]), "+f"(c[3])
        : "r"(a[0]), "r"(a[1]), "r"(a[2]), "r"(a[3]), "r"(b0), "r"(b1));
}

// ---------------- prep: one warp per row, smem-staged, fully-coalesced stores ----------------
__global__ void prep_AB_kernel(const float* __restrict__ query,
                               const float* __restrict__ key,
                               float* __restrict__ out) {
    __shared__ float sq[8][148];
    __shared__ float sk[8][148];
    const int lane = threadIdx.x & 31;
    const int w    = threadIdx.x >> 5;
    const int p    = blockIdx.x * 8 + w;
    const bool pq  = (p < NQ);
    const bool pk  = (p < NK);

    // stage key row (coalesced) and query patch gather
    const float* krow = key + (size_t)p * D_;
    const int ppos = pq ? (p / HO) * H + (p % HO) : 0;
    #pragma unroll
    for (int e = lane; e < 147; e += 32) {
        sk[w][e] = pk ? __ldg(krow + e) : 0.0f;
        sq[w][e] = pq ? __ldg(query + d_lut.v[e] + ppos) : 0.0f;
    }
    __syncwarp();

    // ||k||^2 via warp xor-reduce
    float s = 0.0f;
    #pragma unroll
    for (int e = lane; e < 147; e += 32) {
        float v = sk[w][e];
        s = fmaf(v, v, s);
    }
    #pragma unroll
    for (int off = 16; off > 0; off >>= 1)
        s += __shfl_xor_sync(0xffffffffu, s, off);
    const float hkn = -0.5f * s;
    const __half kb1 = __float2half_rn(hkn);
    const __half kb2 = __float2half_rn(hkn - __half2float(kb1));

    // write phase: lanes 0..27, block (lane + 28*g2)*8 -> contiguous 448B per phase
    if (lane < 28) {
        #pragma unroll
        for (int g2 = 0; g2 < 2; ++g2) {
            int k0 = (lane + 28 * g2) * 8;
            __half va[8], vb[8];
            #pragma unroll
            for (int j = 0; j < 8; ++j) {
                int k = k0 + j;
                if (k < 441) {
                    int term, kk;
                    if (k < 147)      { term = 0; kk = k; }
                    else if (k < 294) { term = 1; kk = k - 147; }
                    else              { term = 2; kk = k - 294; }
                    float xq = sq[w][kk];
                    __half bq = __float2half_rn(xq);
                    va[j] = (term == 1) ? __float2half_rn(xq - __half2float(bq)) : bq;
                    float xk = sk[w][kk];
                    __half bk = __float2half_rn(xk);
                    vb[j] = (term == 2) ? __float2half_rn(xk - __half2float(bk)) : bk;
                } else if (k == 441) {
                    va[j] = __float2half_rn(1.0f);
                    vb[j] = pk ? kb1 : __float2half_rn(-60000.0f);  // sentinel pad rows
                } else if (k == 442) {
                    va[j] = __float2half_rn(1.0f);
                    vb[j] = pk ? kb2 : __float2half_rn(0.0f);
                } else {
                    va[j] = __float2half_rn(0.0f);
                    vb[j] = __float2half_rn(0.0f);
                }
            }
            *reinterpret_cast<uint4*>(&g_A[(size_t)p * KT + k0]) = *reinterpret_cast<uint4*>(va);
            *reinterpret_cast<uint4*>(&g_B[(size_t)p * KT + k0]) = *reinterpret_cast<uint4*>(vb);
        }
    }

    // init g_cand and zero out
    int t = blockIdx.x * 256 + threadIdx.x;
    if (t < NR) g_cand[t] = 0xFFFFFFFFFFFFFFFFull;
    if (t < 3 * NPIX) out[t] = 0.0f;
}

// ---------------- main mma.sync fp16 GEMM + argmax(acc) ----------------
// smem: 3 x (As 16KB | Bs 16KB)
#define BUF_BYTES 32768
#define SMEM_TOTAL (3 * BUF_BYTES)

__global__ __launch_bounds__(256, 2) void nn_mma_kernel() {
    extern __shared__ __align__(128) char smem[];
    uint32_t sb = smem_u32(smem);

    const int tid = threadIdx.x;
    const int l   = tid & 31;
    const int wid = tid >> 5;
    const int wm  = wid & 3;    // 4 M-warps (32 rows each)
    const int wn  = wid >> 2;   // 2 N-warps (64 cols each)
    const int m0  = blockIdx.x * BM;
    const int n0  = blockIdx.y * BN;

    const __half* Ag = g_A + (size_t)m0 * KT;
    const __half* Bg = g_B + (size_t)n0 * KT;

    const int a_r  = (l & 7) | (((l >> 3) & 1) << 3);
    const int a_kh = (l >> 4) & 1;
    const int b_r  = (l & 7) | (((l >> 4) & 1) << 3);
    const int b_kh = (l >> 3) & 1;

    float acc[2][8][4];
    #pragma unroll
    for (int mi = 0; mi < 2; ++mi)
        #pragma unroll
        for (int ni = 0; ni < 8; ++ni)
            #pragma unroll
            for (int c = 0; c < 4; ++c) acc[mi][ni][c] = 0.0f;

    auto issue = [&](int kt) {
        uint32_t ab = sb + (uint32_t)(kt % 3) * BUF_BYTES;
        uint32_t bb = ab + 16384;
        const __half* As = Ag + kt * BK;
        const __half* Bs = Bg + kt * BK;
        #pragma unroll
        for (int i = tid; i < 1024; i += 256) {
            int r = i >> 3, c = i & 7;
            uint32_t off = ((uint32_t)r << 7) | ((uint32_t)(c ^ (r & 7)) << 4);
            cp16(ab + off, As + (size_t)r * KT + c * 8);
            cp16(bb + off, Bs + (size_t)r * KT + c * 8);
        }
        asm volatile("cp.async.commit_group;" ::: "memory");
    };

    issue(0);
    issue(1);

    #pragma unroll
    for (int kt = 0; kt < KTILES; ++kt) {
        if (kt + 1 < KTILES) {
            asm volatile("cp.async.wait_group 1;" ::: "memory");
        } else {
            asm volatile("cp.async.wait_group 0;" ::: "memory");
        }
        __syncthreads();

        if (kt + 2 < KTILES) issue(kt + 2);

        uint32_t ab = sb + (uint32_t)(kt % 3) * BUF_BYTES;
        uint32_t bb = ab + 16384;

        #pragma unroll
        for (int ks = 0; ks < 4; ++ks) {
            uint32_t a[2][4];
            #pragma unroll
            for (int mi = 0; mi < 2; ++mi) {
                int row = wm * 32 + mi * 16 + a_r;
                uint32_t chunk = (uint32_t)((ks * 2 + a_kh) ^ (row & 7));
                ldmatrix_x4(a[mi], ab + ((uint32_t)row << 7) + (chunk << 4));
            }
            #pragma unroll
            for (int nj = 0; nj < 4; ++nj) {
                uint32_t b4[4];
                int nrow = wn * 64 + nj * 16 + b_r;
                uint32_t chunk = (uint32_t)((ks * 2 + b_kh) ^ (nrow & 7));
                ldmatrix_x4(b4, bb + ((uint32_t)nrow << 7) + (chunk << 4));
                #pragma unroll
                for (int mi = 0; mi < 2; ++mi) {
                    mma_f16(acc[mi][2 * nj],     a[mi], b4[0], b4[1]);
                    mma_f16(acc[mi][2 * nj + 1], a[mi], b4[2], b4[3]);
                }
            }
        }
        // no trailing sync: next iteration's sync protects buffer reuse
    }

    // ---- argmax(acc) epilogue (kn folded into GEMM) ----
    const int q = l & 3, g = l >> 2;
    float best[4];
    int   bidx[4];
    #pragma unroll
    for (int s = 0; s < 4; ++s) { best[s] = -3.402823466e38f; bidx[s] = 0; }

    #pragma unroll
    for (int mi = 0; mi < 2; ++mi) {
        #pragma unroll
        for (int ni = 0; ni < 8; ++ni) {
            int col0 = n0 + wn * 64 + ni * 8 + q * 2;
            #pragma unroll
            for (int h = 0; h < 2; ++h) {
                int s = mi * 2 + h;
                float a0 = acc[mi][ni][h * 2];
                float a1 = acc[mi][ni][h * 2 + 1];
                if (a0 > best[s]) { best[s] = a0; bidx[s] = col0; }
                if (a1 > best[s]) { best[s] = a1; bidx[s] = col0 + 1; }
            }
        }
    }

    #pragma unroll
    for (int s = 0; s < 4; ++s) {
        float b = best[s];
        int   i = bidx[s];
        #pragma unroll
        for (int off = 1; off <= 2; off <<= 1) {
            float ob = __shfl_xor_sync(0xffffffffu, b, off);
            int   oi = __shfl_xor_sync(0xffffffffu, i, off);
            if (ob > b || (ob == b && oi < i)) { b = ob; i = oi; }
        }
        if (q == 0) {
            int row = m0 + wm * 32 + (s >> 1) * 16 + (s & 1) * 8 + g;
            if (row < NQ)
                atomicMin(&g_cand[row], (((ull)fkey(-b)) << 32) | (unsigned)i);
        }
    }
}

// ---------------- fold scatter: one warp per patch, pre-divided atomics ----------------
__global__ void scatter_kernel(const float* __restrict__ value, float* __restrict__ out) {
    int w    = blockIdx.x * 8 + (threadIdx.x >> 5);   // patch index
    int lane = threadIdx.x & 31;
    if (w >= NQ) return;
    int row = (int)(unsigned)(g_cand[w] & 0xffffffffull);
    int pi = w / HO, pj = w - (w / HO) * HO;
    const float* vr = value + (size_t)row * D_;
    #pragma unroll
    for (int e = lane; e < D_; e += 32) {
        uint32_t u = __ldg(&d_lut.v[e]);           // qoff = c*9216 + i*96 + j
        int c = (int)u / NPIX;
        int rem = (int)u - c * NPIX;
        int y = pi + rem / H;
        int x = pj + (rem - (rem / H) * H);
        int npi = min(HO - 1, y) - max(0, y - 6) + 1;
        int npj = min(HO - 1, x) - max(0, x - 6) + 1;
        float inv = __frcp_rn((float)(npi * npj));
        atomicAdd(&out[c * NPIX + y * H + x], __ldg(vr + e) * inv);
    }
}

// ---------------- launch ----------------
extern "C" void kernel_launch(void* const* d_in, const int* in_sizes, int n_in,
                              void* d_out, int out_size) {
    const float* query = (const float*)d_in[0];
    const float* key   = (const float*)d_in[1];
    const float* value = (const float*)d_in[2];
    float* out = (float*)d_out;

    {
        prep_AB_kernel<<<NR / 8, 256>>>(query, key, out);   // 1024 blocks, warp-per-row
    }
    {
        cudaFuncSetAttribute(nn_mma_kernel,
                             cudaFuncAttributeMaxDynamicSharedMemorySize, SMEM_TOTAL);
        dim3 grid(NR / BM, NR / BN);               // 64 x 64
        nn_mma_kernel<<<grid, 256, SMEM_TOTAL>>>();
    }
    {
        scatter_kernel<<<(NQ + 7) / 8, 256>>>(value, out);
    }
}

// round 17
// speedup vs baseline: 1.2005x; 1.0111x over previous
#include <cuda_runtime.h>
#include <cuda_fp16.h>
#include <cstdint>

typedef unsigned long long ull;

// ---------------- problem constants ----------------
#define NQ 8100
#define NK 8100
#define D_ 147
#define HO 90
#define H  96
#define NPIX (H * H)       // 9216

#define KT    448          // fp16: [b(147)|s(147)|b(147)|kn cols|pad]
#define NR    8192
#define BM    128
#define BN    128
#define BK    64
#define KTILES 7           // 448/64

// ---------------- device scratch ----------------
__device__ __align__(256) __half g_A[(size_t)NR * KT];  // [qb | qs | qb | 1 1 0..]
__device__ __align__(256) __half g_B[(size_t)NR * KT];  // [kb | kb | ks | -kn/2 split]
__device__ ull   g_cand[NR];

// ---------------- compile-time LUTs ----------------
// qoff[e] = c*NPIX + i*H + j   (query gather offsets)
struct LutT { uint32_t v[160]; };
constexpr LutT make_lut() {
    LutT l{};
    for (int e = 0; e < 147; ++e) {
        int c = e / 49, rr = e % 49, i = rr / 7, j = rr % 7;
        l.v[e] = (uint32_t)(c * NPIX + i * H + j);
    }
    return l;
}
__device__ const LutT d_lut = make_lut();

// packed (c<<16 | i<<8 | j) for scatter (no divisions)
constexpr LutT make_cij() {
    LutT l{};
    for (int e = 0; e < 147; ++e) {
        int c = e / 49, rr = e % 49, i = rr / 7, j = rr % 7;
        l.v[e] = ((uint32_t)c << 16) | ((uint32_t)i << 8) | (uint32_t)j;
    }
    return l;
}
__device__ const LutT d_cij = make_cij();

// ---------------- helpers ----------------
__device__ __forceinline__ uint32_t smem_u32(const void* p) {
    uint32_t a;
    asm("{ .reg .u64 t; cvta.to.shared.u64 t, %1; cvt.u32.u64 %0, t; }" : "=r"(a) : "l"(p));
    return a;
}
__device__ __forceinline__ unsigned fkey(float f) {
    unsigned u = __float_as_uint(f);
    return (u & 0x80000000u) ? ~u : (u | 0x80000000u);
}
__device__ __forceinline__ void cp16(uint32_t dst, const void* src) {
    asm volatile("cp.async.cg.shared.global [%0], [%1], 16;" :: "r"(dst), "l"(src));
}
__device__ __forceinline__ void ldmatrix_x4(uint32_t* r, uint32_t addr) {
    asm volatile("ldmatrix.sync.aligned.m8n8.x4.shared.b16 {%0,%1,%2,%3}, [%4];"
                 : "=r"(r[0]), "=r"(r[1]), "=r"(r[2]), "=r"(r[3]) : "r"(addr));
}
__device__ __forceinline__ void mma_f16(float* c, const uint32_t* a, uint32_t b0, uint32_t b1) {
    asm volatile(
        "mma.sync.aligned.m16n8k16.row.col.f32.f16.f16.f32 "
        "{%0,%1,%2,%3}, {%4,%5,%6,%7}, {%8,%9}, {%0,%1,%2,%3};"
        : "+f"(c[0]), "+f"(c[1]), "+f"(c[2]), "+f"(c[3])
        : "r"(a[0]), "r"(a[1]), "r"(a[2]), "r"(a[3]), "r"(b0), "r"(b1));
}

// ---------------- prep: one warp per row, smem-staged, coalesced stores ----------------
__global__ void prep_AB_kernel(const float* __restrict__ query,
                               const float* __restrict__ key,
                               float* __restrict__ out) {
    __shared__ float sq[8][148];
    __shared__ float sk[8][148];
    const int lane = threadIdx.x & 31;
    const int w    = threadIdx.x >> 5;
    const int p    = blockIdx.x * 8 + w;
    const bool pq  = (p < NQ);
    const bool pk  = (p < NK);

    const float* krow = key + (size_t)p * D_;
    const int ppos = pq ? (p / HO) * H + (p % HO) : 0;
    #pragma unroll
    for (int e = lane; e < 147; e += 32) {
        sk[w][e] = pk ? __ldg(krow + e) : 0.0f;
        sq[w][e] = pq ? __ldg(query + d_lut.v[e] + ppos) : 0.0f;
    }
    __syncwarp();

    float s = 0.0f;
    #pragma unroll
    for (int e = lane; e < 147; e += 32) {
        float v = sk[w][e];
        s = fmaf(v, v, s);
    }
    #pragma unroll
    for (int off = 16; off > 0; off >>= 1)
        s += __shfl_xor_sync(0xffffffffu, s, off);
    const float hkn = -0.5f * s;
    const __half kb1 = __float2half_rn(hkn);
    const __half kb2 = __float2half_rn(hkn - __half2float(kb1));

    if (lane < 28) {
        #pragma unroll
        for (int g2 = 0; g2 < 2; ++g2) {
            int k0 = (lane + 28 * g2) * 8;
            __half va[8], vb[8];
            #pragma unroll
            for (int j = 0; j < 8; ++j) {
                int k = k0 + j;
                if (k < 441) {
                    int term, kk;
                    if (k < 147)      { term = 0; kk = k; }
                    else if (k < 294) { term = 1; kk = k - 147; }
                    else              { term = 2; kk = k - 294; }
                    float xq = sq[w][kk];
                    __half bq = __float2half_rn(xq);
                    va[j] = (term == 1) ? __float2half_rn(xq - __half2float(bq)) : bq;
                    float xk = sk[w][kk];
                    __half bk = __float2half_rn(xk);
                    vb[j] = (term == 2) ? __float2half_rn(xk - __half2float(bk)) : bk;
                } else if (k == 441) {
                    va[j] = __float2half_rn(1.0f);
                    vb[j] = pk ? kb1 : __float2half_rn(-60000.0f);
                } else if (k == 442) {
                    va[j] = __float2half_rn(1.0f);
                    vb[j] = pk ? kb2 : __float2half_rn(0.0f);
                } else {
                    va[j] = __float2half_rn(0.0f);
                    vb[j] = __float2half_rn(0.0f);
                }
            }
            *reinterpret_cast<uint4*>(&g_A[(size_t)p * KT + k0]) = *reinterpret_cast<uint4*>(va);
            *reinterpret_cast<uint4*>(&g_B[(size_t)p * KT + k0]) = *reinterpret_cast<uint4*>(vb);
        }
    }

    int t = blockIdx.x * 256 + threadIdx.x;
    if (t < NR) g_cand[t] = 0xFFFFFFFFFFFFFFFFull;
    if (t < 3 * NPIX) out[t] = 0.0f;
}

// ---------------- main mma.sync fp16 GEMM + argmax(acc) ----------------
#define BUF_BYTES 32768
#define SMEM_TOTAL (3 * BUF_BYTES)

__global__ __launch_bounds__(256, 2) void nn_mma_kernel() {
    extern __shared__ __align__(128) char smem[];
    uint32_t sb = smem_u32(smem);

    const int tid = threadIdx.x;
    const int l   = tid & 31;
    const int wid = tid >> 5;
    const int wm  = wid & 3;
    const int wn  = wid >> 2;
    const int m0  = blockIdx.x * BM;
    const int n0  = blockIdx.y * BN;

    const __half* Ag = g_A + (size_t)m0 * KT;
    const __half* Bg = g_B + (size_t)n0 * KT;

    const int a_r  = (l & 7) | (((l >> 3) & 1) << 3);
    const int a_kh = (l >> 4) & 1;
    const int b_r  = (l & 7) | (((l >> 4) & 1) << 3);
    const int b_kh = (l >> 3) & 1;

    float acc[2][8][4];
    #pragma unroll
    for (int mi = 0; mi < 2; ++mi)
        #pragma unroll
        for (int ni = 0; ni < 8; ++ni)
            #pragma unroll
            for (int c = 0; c < 4; ++c) acc[mi][ni][c] = 0.0f;

    auto issue = [&](int kt) {
        uint32_t ab = sb + (uint32_t)(kt % 3) * BUF_BYTES;
        uint32_t bb = ab + 16384;
        const __half* As = Ag + kt * BK;
        const __half* Bs = Bg + kt * BK;
        #pragma unroll
        for (int i = tid; i < 1024; i += 256) {
            int r = i >> 3, c = i & 7;
            uint32_t off = ((uint32_t)r << 7) | ((uint32_t)(c ^ (r & 7)) << 4);
            cp16(ab + off, As + (size_t)r * KT + c * 8);
            cp16(bb + off, Bs + (size_t)r * KT + c * 8);
        }
        asm volatile("cp.async.commit_group;" ::: "memory");
    };

    // B-fragment address for (ks, nj) in buffer bb
    auto b_addr = [&](uint32_t bb, int ks, int nj) -> uint32_t {
        int nrow = wn * 64 + nj * 16 + b_r;
        uint32_t chunk = (uint32_t)((ks * 2 + b_kh) ^ (nrow & 7));
        return bb + ((uint32_t)nrow << 7) + (chunk << 4);
    };

    issue(0);
    issue(1);

    #pragma unroll
    for (int kt = 0; kt < KTILES; ++kt) {
        if (kt + 1 < KTILES) {
            asm volatile("cp.async.wait_group 1;" ::: "memory");
        } else {
            asm volatile("cp.async.wait_group 0;" ::: "memory");
        }
        __syncthreads();

        if (kt + 2 < KTILES) issue(kt + 2);

        uint32_t ab = sb + (uint32_t)(kt % 3) * BUF_BYTES;
        uint32_t bb = ab + 16384;

        // B-fragment software pipeline: prefetch (ks,nj)+1 before current MMAs
        uint32_t bfr[2][4];
        ldmatrix_x4(bfr[0], b_addr(bb, 0, 0));

        #pragma unroll
        for (int ks = 0; ks < 4; ++ks) {
            uint32_t a[2][4];
            #pragma unroll
            for (int mi = 0; mi < 2; ++mi) {
                int row = wm * 32 + mi * 16 + a_r;
                uint32_t chunk = (uint32_t)((ks * 2 + a_kh) ^ (row & 7));
                ldmatrix_x4(a[mi], ab + ((uint32_t)row << 7) + (chunk << 4));
            }
            #pragma unroll
            for (int nj = 0; nj < 4; ++nj) {
                int cur = (ks * 4 + nj) & 1;
                // prefetch next B fragment (if any remain in this kt)
                if (ks * 4 + nj < 15) {
                    int nks = (nj == 3) ? ks + 1 : ks;
                    int nnj = (nj == 3) ? 0 : nj + 1;
                    ldmatrix_x4(bfr[cur ^ 1], b_addr(bb, nks, nnj));
                }
                #pragma unroll
                for (int mi = 0; mi < 2; ++mi) {
                    mma_f16(acc[mi][2 * nj],     a[mi], bfr[cur][0], bfr[cur][1]);
                    mma_f16(acc[mi][2 * nj + 1], a[mi], bfr[cur][2], bfr[cur][3]);
                }
            }
        }
        // no trailing sync: next iteration's sync protects buffer reuse
    }

    // ---- argmax(acc) epilogue (kn folded into GEMM) ----
    const int q = l & 3, g = l >> 2;
    float best[4];
    int   bidx[4];
    #pragma unroll
    for (int s = 0; s < 4; ++s) { best[s] = -3.402823466e38f; bidx[s] = 0; }

    #pragma unroll
    for (int mi = 0; mi < 2; ++mi) {
        #pragma unroll
        for (int ni = 0; ni < 8; ++ni) {
            int col0 = n0 + wn * 64 + ni * 8 + q * 2;
            #pragma unroll
            for (int h = 0; h < 2; ++h) {
                int s = mi * 2 + h;
                float a0 = acc[mi][ni][h * 2];
                float a1 = acc[mi][ni][h * 2 + 1];
                if (a0 > best[s]) { best[s] = a0; bidx[s] = col0; }
                if (a1 > best[s]) { best[s] = a1; bidx[s] = col0 + 1; }
            }
        }
    }

    #pragma unroll
    for (int s = 0; s < 4; ++s) {
        float b = best[s];
        int   i = bidx[s];
        #pragma unroll
        for (int off = 1; off <= 2; off <<= 1) {
            float ob = __shfl_xor_sync(0xffffffffu, b, off);
            int   oi = __shfl_xor_sync(0xffffffffu, i, off);
            if (ob > b || (ob == b && oi < i)) { b = ob; i = oi; }
        }
        if (q == 0) {
            int row = m0 + wm * 32 + (s >> 1) * 16 + (s & 1) * 8 + g;
            if (row < NQ)
                atomicMin(&g_cand[row], (((ull)fkey(-b)) << 32) | (unsigned)i);
        }
    }
}

// ---------------- fold scatter: one warp per patch, LUT-decoded, pre-divided ----------------
__global__ void scatter_kernel(const float* __restrict__ value, float* __restrict__ out) {
    int w    = blockIdx.x * 8 + (threadIdx.x >> 5);
    int lane = threadIdx.x & 31;
    if (w >= NQ) return;
    int row = (int)(unsigned)(g_cand[w] & 0xffffffffull);
    int pi = w / HO, pj = w - (w / HO) * HO;
    const float* vr = value + (size_t)row * D_;
    #pragma unroll
    for (int e = lane; e < D_; e += 32) {
        uint32_t u = __ldg(&d_cij.v[e]);
        int c = (int)(u >> 16);
        int y = pi + (int)((u >> 8) & 0xffu);
        int x = pj + (int)(u & 0xffu);
        int npi = min(HO - 1, y) - max(0, y - 6) + 1;
        int npj = min(HO - 1, x) - max(0, x - 6) + 1;
        float inv = __frcp_rn((float)(npi * npj));
        atomicAdd(&out[c * NPIX + y * H + x], __ldg(vr + e) * inv);
    }
}

// ---------------- launch ----------------
extern "C" void kernel_launch(void* const* d_in, const int* in_sizes, int n_in,
                              void* d_out, int out_size) {
    const float* query = (const float*)d_in[0];
    const float* key   = (const float*)d_in[1];
    const float* value = (const float*)d_in[2];
    float* out = (float*)d_out;

    {
        prep_AB_kernel<<<NR / 8, 256>>>(query, key, out);
    }
    {
        cudaFuncSetAttribute(nn_mma_kernel,
                             cudaFuncAttributeMaxDynamicSharedMemorySize, SMEM_TOTAL);
        dim3 grid(NR / BM, NR / BN);               // 64 x 64
        nn_mma_kernel<<<grid, 256, SMEM_TOTAL>>>();
    }
    {
        scatter_kernel<<<(NQ + 7) / 8, 256>>>(value, out);
    }
}